// round 8
// baseline (speedup 1.0000x reference)
#include <cuda_runtime.h>
#include <cuda_fp16.h>
#include <math.h>
#include <stdint.h>

// ---------------------------------------------------------------------------
// MoE grouped MLP via fp16 mma.sync m16n8k16 with static scaling.
// fp16 mantissa == tf32 mantissa (10 bits) -> same accuracy, 2x MAC/inst.
// T=4096 H=2048 I=1408 E=8 K=2; rows = 8192.
// ---------------------------------------------------------------------------
#define T_TOK 4096
#define H_DIM 2048
#define I_DIM 1408
#define N_EXP 8
#define TOPK  2
#define R_ROWS (T_TOK * TOPK)
#define BM 128
#define MAX_TILES (R_ROWS / BM + N_EXP)   // 72

#define BN 64
#define BK 32
#define STAGES 4
#define NK1 (H_DIM / BK)                   // 64
#define NK2 (I_DIM / BK)                   // 44

#define SH 40                              // SMEM row stride in halfs (conflict-free)
#define AS_H (BM * SH)                     // 5120 halfs
#define BS_H (BN * SH)                     // 2560 halfs
#define G1_SMEM ((STAGES * (AS_H + 2 * BS_H)) * 2)   // 81920 B
#define G2_SMEM ((STAGES * (AS_H + BS_H)) * 2)       // 61440 B

#define XP_ROWS  (R_ROWS + 128)
#define ACT_ROWS (R_ROWS + 128)

// static scaling: x*64, W*64, act*4096
#define S_IN   64.0f
#define DESC1  (1.0f / (64.0f * 64.0f))            // after GEMM1
#define S_ACT  4096.0f
#define DESC2  (1.0f / (4096.0f * 64.0f))          // after GEMM2

// ---- device-global scratch ----
__device__ int    g_counts[N_EXP];
__device__ int    g_cursor[N_EXP];
__device__ int    g_tile_e[MAX_TILES];
__device__ int    g_tile_row0[MAX_TILES];
__device__ int    g_tile_rows[MAX_TILES];
__device__ int    g_num_tiles;
__device__ int    g_row_t[R_ROWS];
__device__ float  g_row_p[R_ROWS];
__device__ __half g_xp[(size_t)XP_ROWS * H_DIM];             // scaled fp16 input
__device__ __half g_act[(size_t)ACT_ROWS * I_DIM];           // scaled fp16 activations
__device__ __half g_gate_t[(size_t)N_EXP * I_DIM * H_DIM];   // [E][I][H] col-major B
__device__ __half g_up_t  [(size_t)N_EXP * I_DIM * H_DIM];
__device__ __half g_down_t[(size_t)N_EXP * H_DIM * I_DIM];   // [E][H][I]

// ---------------------------------------------------------------------------
__device__ __forceinline__ void cp16(void* dst, const void* src) {
    uint32_t d = (uint32_t)__cvta_generic_to_shared(dst);
    asm volatile("cp.async.cg.shared.global [%0], [%1], 16;" :: "r"(d), "l"(src) : "memory");
}
#define CP_COMMIT() asm volatile("cp.async.commit_group;" ::: "memory")
#define CP_WAIT2()  asm volatile("cp.async.wait_group 2;" ::: "memory")

// D += A(16x16,row) * B(16x8,col), fp16 in / fp32 accum
#define MMA_F16(d, a, b0, b1)                                                \
    asm volatile("mma.sync.aligned.m16n8k16.row.col.f32.f16.f16.f32 "        \
        "{%0,%1,%2,%3}, {%4,%5,%6,%7}, {%8,%9}, {%0,%1,%2,%3};"              \
        : "+f"((d)[0]), "+f"((d)[1]), "+f"((d)[2]), "+f"((d)[3])             \
        : "r"((a)[0]), "r"((a)[1]), "r"((a)[2]), "r"((a)[3]),                \
          "r"(b0), "r"(b1))

__device__ __forceinline__ uint32_t ldh2(const __half* p) {
    return *(const uint32_t*)p;
}

// ---------------------------------------------------------------------------
// prep kernels
// ---------------------------------------------------------------------------
__global__ void k_zero_counts() { if (threadIdx.x < N_EXP) g_counts[threadIdx.x] = 0; }

__global__ void k_hist(const int* __restrict__ sel) {
    int f = blockIdx.x * blockDim.x + threadIdx.x;
    if (f < R_ROWS) {
        int t = f % T_TOK, k = f / T_TOK;
        atomicAdd(&g_counts[sel[t * TOPK + k]], 1);
    }
}

__global__ void k_prep() {
    int off = 0, nt = 0;
    for (int e = 0; e < N_EXP; ++e) {
        int c = g_counts[e];
        g_cursor[e] = off;
        for (int r0 = 0; r0 < c; r0 += BM) {
            g_tile_e[nt] = e; g_tile_row0[nt] = off + r0;
            g_tile_rows[nt] = min(BM, c - r0); ++nt;
        }
        off += c;
    }
    g_num_tiles = nt;
}

__global__ void k_scatter(const int* __restrict__ sel, const float* __restrict__ rw) {
    int f = blockIdx.x * blockDim.x + threadIdx.x;
    if (f < R_ROWS) {
        int t = f % T_TOK, k = f / T_TOK;
        int e = sel[t * TOPK + k];
        int d = atomicAdd(&g_cursor[e], 1);
        g_row_t[d] = t;
        g_row_p[d] = rw[t * TOPK + k];
    }
}

__global__ void k_zero_out(float4* __restrict__ out, int n4) {
    int i = blockIdx.x * blockDim.x + threadIdx.x;
    if (i < n4) out[i] = make_float4(0.f, 0.f, 0.f, 0.f);
}

// gather rows, scale by 64, convert to fp16
__global__ void k_permute(const float* __restrict__ hid) {
    int r = blockIdx.x;
    int t = g_row_t[r];
    const float4* src = (const float4*)(hid + (size_t)t * H_DIM);
    __half2* dst = (__half2*)(g_xp + (size_t)r * H_DIM);
    for (int i = threadIdx.x; i < H_DIM / 4; i += blockDim.x) {
        float4 v = src[i];
        dst[2*i]   = __floats2half2_rn(v.x * S_IN, v.y * S_IN);
        dst[2*i+1] = __floats2half2_rn(v.z * S_IN, v.w * S_IN);
    }
}

// transpose + scale + fp16 convert: in [R,C] per expert -> out [C,R]
template<int R, int C>
__global__ void k_transpose(const float* __restrict__ in, __half* __restrict__ out) {
    __shared__ float tile[32][33];
    int e = blockIdx.z;
    in  += (size_t)e * R * C;
    out += (size_t)e * R * C;
    int c0 = blockIdx.x * 32, r0 = blockIdx.y * 32;
    int x = threadIdx.x, y = threadIdx.y;
    #pragma unroll
    for (int dy = 0; dy < 32; dy += 8)
        tile[y + dy][x] = in[(size_t)(r0 + y + dy) * C + c0 + x];
    __syncthreads();
    #pragma unroll
    for (int dy = 0; dy < 32; dy += 8)
        out[(size_t)(c0 + y + dy) * R + r0 + x] = __float2half_rn(tile[x][y + dy] * S_IN);
}

// ---------------------------------------------------------------------------
// GEMM1: act = silu(xp @ gate^T) * (xp @ up^T), fp16 mma, 128x64 tiles.
// 256 threads = 8 warps (4M x 2N), warp tile 32x32.
// ---------------------------------------------------------------------------
__global__ __launch_bounds__(256, 2)
void k_gemm1_mma(const __half* __restrict__ xp,
                 const __half* __restrict__ gt,
                 const __half* __restrict__ ut) {
    const int tile = blockIdx.x;
    if (tile >= g_num_tiles) return;
    const int e    = g_tile_e[tile];
    const int row0 = g_tile_row0[tile];
    const int rows = g_tile_rows[tile];
    const int n0   = blockIdx.y * BN;

    extern __shared__ __half sm[];
    __half* As = sm;                          // [S][128][40]
    __half* Bg = sm + STAGES * AS_H;          // [S][64][40]
    __half* Bu = Bg + STAGES * BS_H;

    const int tid  = threadIdx.x;
    const int lane = tid & 31, wid = tid >> 5;
    const int wm = wid & 3, wn = wid >> 2;
    const int lg = lane >> 2, lt = lane & 3;

    const __half* arow = xp + (size_t)row0 * H_DIM;
    const __half* gte  = gt + ((size_t)e * I_DIM + n0) * H_DIM;
    const __half* ute  = ut + ((size_t)e * I_DIM + n0) * H_DIM;

    // loaders: A = 128 rows x 4 chunks (2/thread), B = 64 x 4 (1/thread each)
    const int alr = tid >> 1, alc = (tid & 1) * 2;   // A row, first chunk
    const int blr = tid >> 2, blc = tid & 3;         // B row, chunk

    float accg[2][4][4], accu[2][4][4];
    #pragma unroll
    for (int a = 0; a < 2; ++a)
        #pragma unroll
        for (int b = 0; b < 4; ++b)
            #pragma unroll
            for (int c = 0; c < 4; ++c) { accg[a][b][c] = 0.f; accu[a][b][c] = 0.f; }

    #define G1_LOAD(s, ki) do {                                                   \
        int k0_ = (ki) * BK;                                                      \
        __half* as_ = As + (s) * AS_H;                                            \
        __half* bg_ = Bg + (s) * BS_H;                                            \
        __half* bu_ = Bu + (s) * BS_H;                                            \
        cp16(&as_[alr * SH + alc * 8],       arow + (size_t)alr * H_DIM + k0_ + alc * 8);      \
        cp16(&as_[alr * SH + (alc + 1) * 8], arow + (size_t)alr * H_DIM + k0_ + (alc + 1) * 8);\
        cp16(&bg_[blr * SH + blc * 8],       gte + (size_t)blr * H_DIM + k0_ + blc * 8);       \
        cp16(&bu_[blr * SH + blc * 8],       ute + (size_t)blr * H_DIM + k0_ + blc * 8);       \
    } while (0)

    G1_LOAD(0, 0); CP_COMMIT();
    G1_LOAD(1, 1); CP_COMMIT();
    G1_LOAD(2, 2); CP_COMMIT();

    int slot = 0;
    #pragma unroll 1
    for (int ki = 0; ki < NK1; ++ki) {
        CP_WAIT2();
        __syncthreads();
        if (ki + 3 < NK1) {
            int ns = slot + 3; if (ns >= STAGES) ns -= STAGES;
            G1_LOAD(ns, ki + 3);
        }
        CP_COMMIT();

        const __half* as = As + slot * AS_H;
        const __half* bg = Bg + slot * BS_H;
        const __half* bu = Bu + slot * BS_H;
        #pragma unroll
        for (int ks = 0; ks < 2; ++ks) {
            const int kb = ks * 16 + 2 * lt;
            uint32_t af[2][4];
            #pragma unroll
            for (int mt = 0; mt < 2; ++mt) {
                int m = wm * 32 + mt * 16 + lg;
                af[mt][0] = ldh2(&as[m * SH + kb]);
                af[mt][1] = ldh2(&as[(m + 8) * SH + kb]);
                af[mt][2] = ldh2(&as[m * SH + kb + 8]);
                af[mt][3] = ldh2(&as[(m + 8) * SH + kb + 8]);
            }
            #pragma unroll
            for (int nt = 0; nt < 4; ++nt) {
                int n = wn * 32 + nt * 8 + lg;
                uint32_t bg0 = ldh2(&bg[n * SH + kb]);
                uint32_t bg1 = ldh2(&bg[n * SH + kb + 8]);
                uint32_t bu0 = ldh2(&bu[n * SH + kb]);
                uint32_t bu1 = ldh2(&bu[n * SH + kb + 8]);
                #pragma unroll
                for (int mt = 0; mt < 2; ++mt) {
                    MMA_F16(accg[mt][nt], af[mt], bg0, bg1);
                    MMA_F16(accu[mt][nt], af[mt], bu0, bu1);
                }
            }
        }
        if (++slot == STAGES) slot = 0;
    }
    #undef G1_LOAD

    // epilogue: descale, silu(g)*u, rescale, store fp16
    #pragma unroll
    for (int mt = 0; mt < 2; ++mt) {
        #pragma unroll
        for (int half = 0; half < 2; ++half) {
            int m = wm * 32 + mt * 16 + lg + half * 8;
            if (m < rows) {
                __half* dst = g_act + (size_t)(row0 + m) * I_DIM + n0 + wn * 32;
                #pragma unroll
                for (int nt = 0; nt < 4; ++nt) {
                    float g0 = accg[mt][nt][half * 2 + 0] * DESC1;
                    float u0 = accu[mt][nt][half * 2 + 0] * DESC1;
                    float g1 = accg[mt][nt][half * 2 + 1] * DESC1;
                    float u1 = accu[mt][nt][half * 2 + 1] * DESC1;
                    float a0 = (g0 / (1.f + __expf(-g0))) * u0 * S_ACT;
                    float a1 = (g1 / (1.f + __expf(-g1))) * u1 * S_ACT;
                    *(__half2*)(dst + nt * 8 + 2 * lt) = __floats2half2_rn(a0, a1);
                }
            }
        }
    }
}

// ---------------------------------------------------------------------------
// GEMM2: out[t] += p * descale * (act @ down^T)
// ---------------------------------------------------------------------------
__global__ __launch_bounds__(256, 2)
void k_gemm2_mma(const __half* __restrict__ act,
                 const __half* __restrict__ dt,
                 float* __restrict__ out) {
    const int tile = blockIdx.x;
    if (tile >= g_num_tiles) return;
    const int e    = g_tile_e[tile];
    const int row0 = g_tile_row0[tile];
    const int rows = g_tile_rows[tile];
    const int n0   = blockIdx.y * BN;

    extern __shared__ __half sm[];
    __half* As = sm;
    __half* Bs = sm + STAGES * AS_H;

    const int tid  = threadIdx.x;
    const int lane = tid & 31, wid = tid >> 5;
    const int wm = wid & 3, wn = wid >> 2;
    const int lg = lane >> 2, lt = lane & 3;

    const __half* arow = act + (size_t)row0 * I_DIM;
    const __half* dte  = dt + ((size_t)e * H_DIM + n0) * I_DIM;

    const int alr = tid >> 1, alc = (tid & 1) * 2;
    const int blr = tid >> 2, blc = tid & 3;

    float acc[2][4][4];
    #pragma unroll
    for (int a = 0; a < 2; ++a)
        #pragma unroll
        for (int b = 0; b < 4; ++b)
            #pragma unroll
            for (int c = 0; c < 4; ++c) acc[a][b][c] = 0.f;

    #define G2_LOAD(s, ki) do {                                                   \
        int k0_ = (ki) * BK;                                                      \
        __half* as_ = As + (s) * AS_H;                                            \
        __half* bs_ = Bs + (s) * BS_H;                                            \
        cp16(&as_[alr * SH + alc * 8],       arow + (size_t)alr * I_DIM + k0_ + alc * 8);      \
        cp16(&as_[alr * SH + (alc + 1) * 8], arow + (size_t)alr * I_DIM + k0_ + (alc + 1) * 8);\
        cp16(&bs_[blr * SH + blc * 8],       dte + (size_t)blr * I_DIM + k0_ + blc * 8);       \
    } while (0)

    G2_LOAD(0, 0); CP_COMMIT();
    G2_LOAD(1, 1); CP_COMMIT();
    G2_LOAD(2, 2); CP_COMMIT();

    int slot = 0;
    #pragma unroll 1
    for (int ki = 0; ki < NK2; ++ki) {
        CP_WAIT2();
        __syncthreads();
        if (ki + 3 < NK2) {
            int ns = slot + 3; if (ns >= STAGES) ns -= STAGES;
            G2_LOAD(ns, ki + 3);
        }
        CP_COMMIT();

        const __half* as = As + slot * AS_H;
        const __half* bs = Bs + slot * BS_H;
        #pragma unroll
        for (int ks = 0; ks < 2; ++ks) {
            const int kb = ks * 16 + 2 * lt;
            uint32_t af[2][4];
            #pragma unroll
            for (int mt = 0; mt < 2; ++mt) {
                int m = wm * 32 + mt * 16 + lg;
                af[mt][0] = ldh2(&as[m * SH + kb]);
                af[mt][1] = ldh2(&as[(m + 8) * SH + kb]);
                af[mt][2] = ldh2(&as[m * SH + kb + 8]);
                af[mt][3] = ldh2(&as[(m + 8) * SH + kb + 8]);
            }
            #pragma unroll
            for (int nt = 0; nt < 4; ++nt) {
                int n = wn * 32 + nt * 8 + lg;
                uint32_t b0 = ldh2(&bs[n * SH + kb]);
                uint32_t b1 = ldh2(&bs[n * SH + kb + 8]);
                #pragma unroll
                for (int mt = 0; mt < 2; ++mt)
                    MMA_F16(acc[mt][nt], af[mt], b0, b1);
            }
        }
        if (++slot == STAGES) slot = 0;
    }
    #undef G2_LOAD

    // epilogue: weighted scatter-add with descale
    #pragma unroll
    for (int mt = 0; mt < 2; ++mt) {
        #pragma unroll
        for (int half = 0; half < 2; ++half) {
            int m = wm * 32 + mt * 16 + lg + half * 8;
            if (m < rows) {
                float p = g_row_p[row0 + m] * DESC2;
                int   t = g_row_t[row0 + m];
                float* dst = out + (size_t)t * H_DIM + n0 + wn * 32;
                #pragma unroll
                for (int nt = 0; nt < 4; ++nt) {
                    atomicAdd(dst + nt * 8 + 2 * lt,     acc[mt][nt][half * 2 + 0] * p);
                    atomicAdd(dst + nt * 8 + 2 * lt + 1, acc[mt][nt][half * 2 + 1] * p);
                }
            }
        }
    }
}

// ---------------------------------------------------------------------------
extern "C" void kernel_launch(void* const* d_in, const int* in_sizes, int n_in,
                              void* d_out, int out_size) {
    const float* hid = (const float*)d_in[0];
    const float* rw  = (const float*)d_in[1];
    const int*   sel = (const int*)  d_in[2];
    const float* gw  = (const float*)d_in[3];
    const float* uw  = (const float*)d_in[4];
    const float* dw  = (const float*)d_in[5];
    float* out = (float*)d_out;

    void *p_xp, *p_act, *p_gt, *p_ut, *p_dt;
    cudaGetSymbolAddress(&p_xp,  g_xp);
    cudaGetSymbolAddress(&p_act, g_act);
    cudaGetSymbolAddress(&p_gt,  g_gate_t);
    cudaGetSymbolAddress(&p_ut,  g_up_t);
    cudaGetSymbolAddress(&p_dt,  g_down_t);

    cudaFuncSetAttribute(k_gemm1_mma, cudaFuncAttributeMaxDynamicSharedMemorySize, G1_SMEM);
    cudaFuncSetAttribute(k_gemm2_mma, cudaFuncAttributeMaxDynamicSharedMemorySize, G2_SMEM);

    // routing prep
    k_zero_counts<<<1, 32>>>();
    k_hist<<<R_ROWS / 256, 256>>>(sel);
    k_prep<<<1, 1>>>();
    k_scatter<<<R_ROWS / 256, 256>>>(sel, rw);

    // staging: gather+scale+fp16 A, transpose+scale+fp16 weights
    k_permute<<<R_ROWS, 256>>>(hid);
    {
        dim3 b(32, 8);
        dim3 g_gu(I_DIM / 32, H_DIM / 32, N_EXP);   // [H,I] -> [I,H]
        k_transpose<H_DIM, I_DIM><<<g_gu, b>>>(gw, (__half*)p_gt);
        k_transpose<H_DIM, I_DIM><<<g_gu, b>>>(uw, (__half*)p_ut);
        dim3 g_d(H_DIM / 32, I_DIM / 32, N_EXP);    // [I,H] -> [H,I]
        k_transpose<I_DIM, H_DIM><<<g_d, b>>>(dw, (__half*)p_dt);
    }

    int n4 = (T_TOK * H_DIM) / 4;
    k_zero_out<<<n4 / 256, 256>>>((float4*)out, n4);

    dim3 g1(MAX_TILES, I_DIM / BN);   // 72 x 22
    k_gemm1_mma<<<g1, 256, G1_SMEM>>>((const __half*)p_xp, (const __half*)p_gt, (const __half*)p_ut);

    dim3 g2(MAX_TILES, H_DIM / BN);   // 72 x 32
    k_gemm2_mma<<<g2, 256, G2_SMEM>>>((const __half*)p_act, (const __half*)p_dt, out);
}

// round 10
// speedup vs baseline: 1.1385x; 1.1385x over previous
#include <cuda_runtime.h>
#include <cuda_fp16.h>
#include <math.h>
#include <stdint.h>
#include <string.h>

// ---------------------------------------------------------------------------
// MoE grouped MLP via fp16 mma.sync m16n8k16 + ldmatrix + vector red.
// T=4096 H=2048 I=1408 E=8 K=2; rows = 8192.
// ---------------------------------------------------------------------------
#define T_TOK 4096
#define H_DIM 2048
#define I_DIM 1408
#define N_EXP 8
#define TOPK  2
#define R_ROWS (T_TOK * TOPK)
#define BM 128
#define MAX_TILES (R_ROWS / BM + N_EXP)   // 72

#define BN 64
#define BK 32
#define STAGES 4
#define NK1 (H_DIM / BK)                   // 64
#define NK2 (I_DIM / BK)                   // 44

#define SH 40                              // SMEM row stride (halfs), conflict-free
#define AS_H (BM * SH)                     // 5120 halfs
#define BS_H (BN * SH)                     // 2560 halfs
#define G1_SMEM ((STAGES * (AS_H + 2 * BS_H)) * 2)   // 81920 B
#define G2_SMEM ((STAGES * (AS_H + BS_H)) * 2)       // 61440 B

#define XP_ROWS  (R_ROWS + 128)
#define ACT_ROWS (R_ROWS + 128)

// static scaling: x*64, W*64, act*4096
#define S_IN   64.0f
#define DESC1  (1.0f / (64.0f * 64.0f))
#define S_ACT  4096.0f
#define DESC2  (1.0f / (4096.0f * 64.0f))

// ---- device-global scratch ----
__device__ int    g_counts[N_EXP];
__device__ int    g_cursor[N_EXP];
__device__ int    g_tile_e[MAX_TILES];
__device__ int    g_tile_row0[MAX_TILES];
__device__ int    g_tile_rows[MAX_TILES];
__device__ int    g_num_tiles;
__device__ int    g_row_t[R_ROWS];
__device__ float  g_row_p[R_ROWS];
__device__ __half g_xp[(size_t)XP_ROWS * H_DIM];
__device__ __half g_act[(size_t)ACT_ROWS * I_DIM];
__device__ __half g_gate_t[(size_t)N_EXP * I_DIM * H_DIM];   // [E][I][H]
__device__ __half g_up_t  [(size_t)N_EXP * I_DIM * H_DIM];
__device__ __half g_down_t[(size_t)N_EXP * H_DIM * I_DIM];   // [E][H][I]

// ---------------------------------------------------------------------------
__device__ __forceinline__ uint32_t h2_bits(__half2 h) {
    uint32_t u;
    memcpy(&u, &h, 4);
    return u;
}
__device__ __forceinline__ void cp16(void* dst, const void* src) {
    uint32_t d = (uint32_t)__cvta_generic_to_shared(dst);
    asm volatile("cp.async.cg.shared.global [%0], [%1], 16;" :: "r"(d), "l"(src) : "memory");
}
#define CP_COMMIT() asm volatile("cp.async.commit_group;" ::: "memory")
#define CP_WAIT2()  asm volatile("cp.async.wait_group 2;" ::: "memory")

#define MMA_F16(d, a, b0, b1)                                                \
    asm volatile("mma.sync.aligned.m16n8k16.row.col.f32.f16.f16.f32 "        \
        "{%0,%1,%2,%3}, {%4,%5,%6,%7}, {%8,%9}, {%0,%1,%2,%3};"              \
        : "+f"((d)[0]), "+f"((d)[1]), "+f"((d)[2]), "+f"((d)[3])             \
        : "r"((a)[0]), "r"((a)[1]), "r"((a)[2]), "r"((a)[3]),                \
          "r"(b0), "r"(b1))

#define LDSM4(r, addr)                                                        \
    asm volatile("ldmatrix.sync.aligned.m8n8.x4.shared.b16 {%0,%1,%2,%3}, [%4];" \
        : "=r"((r)[0]), "=r"((r)[1]), "=r"((r)[2]), "=r"((r)[3]) : "r"(addr))

#define REDV2(ptr, v0, v1)                                                    \
    asm volatile("red.global.add.v2.f32 [%0], {%1, %2};"                      \
        :: "l"(ptr), "f"(v0), "f"(v1) : "memory")

// ---------------------------------------------------------------------------
// prep kernels
// ---------------------------------------------------------------------------
__global__ void k_zero_counts() { if (threadIdx.x < N_EXP) g_counts[threadIdx.x] = 0; }

__global__ void k_hist(const int* __restrict__ sel) {
    int f = blockIdx.x * blockDim.x + threadIdx.x;
    if (f < R_ROWS) {
        int t = f % T_TOK, k = f / T_TOK;
        atomicAdd(&g_counts[sel[t * TOPK + k]], 1);
    }
}

__global__ void k_prep() {
    int off = 0, nt = 0;
    for (int e = 0; e < N_EXP; ++e) {
        int c = g_counts[e];
        g_cursor[e] = off;
        for (int r0 = 0; r0 < c; r0 += BM) {
            g_tile_e[nt] = e; g_tile_row0[nt] = off + r0;
            g_tile_rows[nt] = min(BM, c - r0); ++nt;
        }
        off += c;
    }
    g_num_tiles = nt;
}

__global__ void k_scatter(const int* __restrict__ sel, const float* __restrict__ rw) {
    int f = blockIdx.x * blockDim.x + threadIdx.x;
    if (f < R_ROWS) {
        int t = f % T_TOK, k = f / T_TOK;
        int e = sel[t * TOPK + k];
        int d = atomicAdd(&g_cursor[e], 1);
        g_row_t[d] = t;
        g_row_p[d] = rw[t * TOPK + k];
    }
}

__global__ void k_zero_out(float4* __restrict__ out, int n4) {
    int i = blockIdx.x * blockDim.x + threadIdx.x;
    if (i < n4) out[i] = make_float4(0.f, 0.f, 0.f, 0.f);
}

// gather rows, scale by 64, convert fp16, 16B stores
__global__ void k_permute(const float* __restrict__ hid) {
    int r = blockIdx.x;
    int t = g_row_t[r];
    const float4* src = (const float4*)(hid + (size_t)t * H_DIM);
    uint4* dst = (uint4*)(g_xp + (size_t)r * H_DIM);
    for (int i = threadIdx.x; i < H_DIM / 8; i += blockDim.x) {
        float4 v0 = src[2 * i], v1 = src[2 * i + 1];
        uint4 o;
        o.x = h2_bits(__floats2half2_rn(v0.x * S_IN, v0.y * S_IN));
        o.y = h2_bits(__floats2half2_rn(v0.z * S_IN, v0.w * S_IN));
        o.z = h2_bits(__floats2half2_rn(v1.x * S_IN, v1.y * S_IN));
        o.w = h2_bits(__floats2half2_rn(v1.z * S_IN, v1.w * S_IN));
        dst[i] = o;
    }
}

// transpose 64x64 tiles + scale + fp16, half2 (128B-coalesced) writes
template<int R, int C>
__global__ void k_transpose(const float* __restrict__ in, __half* __restrict__ out) {
    __shared__ float tile[64][65];
    int e = blockIdx.z;
    in  += (size_t)e * R * C;
    out += (size_t)e * R * C;
    int c0 = blockIdx.x * 64, r0 = blockIdx.y * 64;
    int x = threadIdx.x, y = threadIdx.y;   // 32 x 8
    #pragma unroll
    for (int dy = 0; dy < 64; dy += 8) {
        const float* src = in + (size_t)(r0 + y + dy) * C + c0;
        tile[y + dy][x]      = src[x];
        tile[y + dy][x + 32] = src[x + 32];
    }
    __syncthreads();
    #pragma unroll
    for (int dy = 0; dy < 64; dy += 8) {
        int oc = c0 + y + dy;
        float v0 = tile[2 * x][y + dy]     * S_IN;
        float v1 = tile[2 * x + 1][y + dy] * S_IN;
        *(__half2*)(out + (size_t)oc * R + r0 + 2 * x) = __floats2half2_rn(v0, v1);
    }
}

// ---------------------------------------------------------------------------
// GEMM1: act = silu(xp @ gate^T) * (xp @ up^T); 128x64 tiles, ldmatrix frags.
// 256 threads = 8 warps (4M x 2N), warp tile 32x32.
// ---------------------------------------------------------------------------
__global__ __launch_bounds__(256, 2)
void k_gemm1_mma(const __half* __restrict__ xp,
                 const __half* __restrict__ gt,
                 const __half* __restrict__ ut) {
    const int tile = blockIdx.x;
    if (tile >= g_num_tiles) return;
    const int e    = g_tile_e[tile];
    const int row0 = g_tile_row0[tile];
    const int rows = g_tile_rows[tile];
    const int n0   = blockIdx.y * BN;

    extern __shared__ __half sm[];
    __half* As = sm;
    __half* Bg = sm + STAGES * AS_H;
    __half* Bu = Bg + STAGES * BS_H;
    const uint32_t su  = (uint32_t)__cvta_generic_to_shared(sm);
    const uint32_t bgu = su + STAGES * AS_H * 2;
    const uint32_t buu = bgu + STAGES * BS_H * 2;

    const int tid  = threadIdx.x;
    const int lane = tid & 31, wid = tid >> 5;
    const int wm = wid & 3, wn = wid >> 2;
    const int lg = lane >> 2, lt = lane & 3;

    // ldmatrix lane offsets (bytes): A rows 0-15 k0/k8; B same pattern
    const uint32_t aoff = (((lane & 7) + ((lane >> 3) & 1) * 8) * SH + (lane >> 4) * 8) * 2;
    const uint32_t boff = (((lane & 7) + (lane >> 4) * 8) * SH + ((lane >> 3) & 1) * 8) * 2;

    const __half* arow = xp + (size_t)row0 * H_DIM;
    const __half* gte  = gt + ((size_t)e * I_DIM + n0) * H_DIM;
    const __half* ute  = ut + ((size_t)e * I_DIM + n0) * H_DIM;

    const int alr = tid >> 1, alc = (tid & 1) * 2;
    const int blr = tid >> 2, blc = tid & 3;

    float accg[2][4][4], accu[2][4][4];
    #pragma unroll
    for (int a = 0; a < 2; ++a)
        #pragma unroll
        for (int b = 0; b < 4; ++b)
            #pragma unroll
            for (int c = 0; c < 4; ++c) { accg[a][b][c] = 0.f; accu[a][b][c] = 0.f; }

    #define G1_LOAD(s, ki) do {                                                   \
        int k0_ = (ki) * BK;                                                      \
        __half* as_ = As + (s) * AS_H;                                            \
        __half* bg_ = Bg + (s) * BS_H;                                            \
        __half* bu_ = Bu + (s) * BS_H;                                            \
        cp16(&as_[alr * SH + alc * 8],       arow + (size_t)alr * H_DIM + k0_ + alc * 8);      \
        cp16(&as_[alr * SH + (alc + 1) * 8], arow + (size_t)alr * H_DIM + k0_ + (alc + 1) * 8);\
        cp16(&bg_[blr * SH + blc * 8],       gte + (size_t)blr * H_DIM + k0_ + blc * 8);       \
        cp16(&bu_[blr * SH + blc * 8],       ute + (size_t)blr * H_DIM + k0_ + blc * 8);       \
    } while (0)

    G1_LOAD(0, 0); CP_COMMIT();
    G1_LOAD(1, 1); CP_COMMIT();
    G1_LOAD(2, 2); CP_COMMIT();

    int slot = 0;
    #pragma unroll 1
    for (int ki = 0; ki < NK1; ++ki) {
        CP_WAIT2();
        __syncthreads();
        if (ki + 3 < NK1) {
            int ns = slot + 3; if (ns >= STAGES) ns -= STAGES;
            G1_LOAD(ns, ki + 3);
        }
        CP_COMMIT();

        const uint32_t asb = su  + slot * AS_H * 2 + (wm * 32) * SH * 2 + aoff;
        const uint32_t bgb = bgu + slot * BS_H * 2 + (wn * 32) * SH * 2 + boff;
        const uint32_t bub = buu + slot * BS_H * 2 + (wn * 32) * SH * 2 + boff;
        #pragma unroll
        for (int ks = 0; ks < 2; ++ks) {
            const uint32_t kb2 = ks * 32;   // ks*16 halfs in bytes
            uint32_t af[2][4], bgr[8], bur[8];
            LDSM4(af[0], asb + kb2);
            LDSM4(af[1], asb + 16 * SH * 2 + kb2);
            LDSM4(&bgr[0], bgb + kb2);
            LDSM4(&bgr[4], bgb + 16 * SH * 2 + kb2);
            LDSM4(&bur[0], bub + kb2);
            LDSM4(&bur[4], bub + 16 * SH * 2 + kb2);
            #pragma unroll
            for (int nt = 0; nt < 4; ++nt) {
                #pragma unroll
                for (int mt = 0; mt < 2; ++mt) {
                    MMA_F16(accg[mt][nt], af[mt], bgr[2 * nt], bgr[2 * nt + 1]);
                    MMA_F16(accu[mt][nt], af[mt], bur[2 * nt], bur[2 * nt + 1]);
                }
            }
        }
        if (++slot == STAGES) slot = 0;
    }
    #undef G1_LOAD

    // epilogue: descale, silu(g)*u, rescale, store fp16
    #pragma unroll
    for (int mt = 0; mt < 2; ++mt) {
        #pragma unroll
        for (int half = 0; half < 2; ++half) {
            int m = wm * 32 + mt * 16 + lg + half * 8;
            if (m < rows) {
                __half* dst = g_act + (size_t)(row0 + m) * I_DIM + n0 + wn * 32;
                #pragma unroll
                for (int nt = 0; nt < 4; ++nt) {
                    float g0 = accg[mt][nt][half * 2 + 0] * DESC1;
                    float u0 = accu[mt][nt][half * 2 + 0] * DESC1;
                    float g1 = accg[mt][nt][half * 2 + 1] * DESC1;
                    float u1 = accu[mt][nt][half * 2 + 1] * DESC1;
                    float a0 = (g0 / (1.f + __expf(-g0))) * u0 * S_ACT;
                    float a1 = (g1 / (1.f + __expf(-g1))) * u1 * S_ACT;
                    *(__half2*)(dst + nt * 8 + 2 * lt) = __floats2half2_rn(a0, a1);
                }
            }
        }
    }
}

// ---------------------------------------------------------------------------
// GEMM2: out[t] += p * descale * (act @ down^T)
// ---------------------------------------------------------------------------
__global__ __launch_bounds__(256, 2)
void k_gemm2_mma(const __half* __restrict__ act,
                 const __half* __restrict__ dt,
                 float* __restrict__ out) {
    const int tile = blockIdx.x;
    if (tile >= g_num_tiles) return;
    const int e    = g_tile_e[tile];
    const int row0 = g_tile_row0[tile];
    const int rows = g_tile_rows[tile];
    const int n0   = blockIdx.y * BN;

    extern __shared__ __half sm[];
    __half* As = sm;
    __half* Bs = sm + STAGES * AS_H;
    const uint32_t su  = (uint32_t)__cvta_generic_to_shared(sm);
    const uint32_t bsu = su + STAGES * AS_H * 2;

    const int tid  = threadIdx.x;
    const int lane = tid & 31, wid = tid >> 5;
    const int wm = wid & 3, wn = wid >> 2;
    const int lg = lane >> 2, lt = lane & 3;

    const uint32_t aoff = (((lane & 7) + ((lane >> 3) & 1) * 8) * SH + (lane >> 4) * 8) * 2;
    const uint32_t boff = (((lane & 7) + (lane >> 4) * 8) * SH + ((lane >> 3) & 1) * 8) * 2;

    const __half* arow = act + (size_t)row0 * I_DIM;
    const __half* dte  = dt + ((size_t)e * H_DIM + n0) * I_DIM;

    const int alr = tid >> 1, alc = (tid & 1) * 2;
    const int blr = tid >> 2, blc = tid & 3;

    float acc[2][4][4];
    #pragma unroll
    for (int a = 0; a < 2; ++a)
        #pragma unroll
        for (int b = 0; b < 4; ++b)
            #pragma unroll
            for (int c = 0; c < 4; ++c) acc[a][b][c] = 0.f;

    #define G2_LOAD(s, ki) do {                                                   \
        int k0_ = (ki) * BK;                                                      \
        __half* as_ = As + (s) * AS_H;                                            \
        __half* bs_ = Bs + (s) * BS_H;                                            \
        cp16(&as_[alr * SH + alc * 8],       arow + (size_t)alr * I_DIM + k0_ + alc * 8);      \
        cp16(&as_[alr * SH + (alc + 1) * 8], arow + (size_t)alr * I_DIM + k0_ + (alc + 1) * 8);\
        cp16(&bs_[blr * SH + blc * 8],       dte + (size_t)blr * I_DIM + k0_ + blc * 8);       \
    } while (0)

    G2_LOAD(0, 0); CP_COMMIT();
    G2_LOAD(1, 1); CP_COMMIT();
    G2_LOAD(2, 2); CP_COMMIT();

    int slot = 0;
    #pragma unroll 1
    for (int ki = 0; ki < NK2; ++ki) {
        CP_WAIT2();
        __syncthreads();
        if (ki + 3 < NK2) {
            int ns = slot + 3; if (ns >= STAGES) ns -= STAGES;
            G2_LOAD(ns, ki + 3);
        }
        CP_COMMIT();

        const uint32_t asb = su  + slot * AS_H * 2 + (wm * 32) * SH * 2 + aoff;
        const uint32_t bsb = bsu + slot * BS_H * 2 + (wn * 32) * SH * 2 + boff;
        #pragma unroll
        for (int ks = 0; ks < 2; ++ks) {
            const uint32_t kb2 = ks * 32;
            uint32_t af[2][4], br[8];
            LDSM4(af[0], asb + kb2);
            LDSM4(af[1], asb + 16 * SH * 2 + kb2);
            LDSM4(&br[0], bsb + kb2);
            LDSM4(&br[4], bsb + 16 * SH * 2 + kb2);
            #pragma unroll
            for (int nt = 0; nt < 4; ++nt) {
                #pragma unroll
                for (int mt = 0; mt < 2; ++mt)
                    MMA_F16(acc[mt][nt], af[mt], br[2 * nt], br[2 * nt + 1]);
            }
        }
        if (++slot == STAGES) slot = 0;
    }
    #undef G2_LOAD

    // epilogue: weighted vector reduce-add with descale
    #pragma unroll
    for (int mt = 0; mt < 2; ++mt) {
        #pragma unroll
        for (int half = 0; half < 2; ++half) {
            int m = wm * 32 + mt * 16 + lg + half * 8;
            if (m < rows) {
                float p = g_row_p[row0 + m] * DESC2;
                int   t = g_row_t[row0 + m];
                float* dst = out + (size_t)t * H_DIM + n0 + wn * 32;
                #pragma unroll
                for (int nt = 0; nt < 4; ++nt) {
                    REDV2(dst + nt * 8 + 2 * lt,
                          acc[mt][nt][half * 2 + 0] * p,
                          acc[mt][nt][half * 2 + 1] * p);
                }
            }
        }
    }
}

// ---------------------------------------------------------------------------
extern "C" void kernel_launch(void* const* d_in, const int* in_sizes, int n_in,
                              void* d_out, int out_size) {
    const float* hid = (const float*)d_in[0];
    const float* rw  = (const float*)d_in[1];
    const int*   sel = (const int*)  d_in[2];
    const float* gw  = (const float*)d_in[3];
    const float* uw  = (const float*)d_in[4];
    const float* dw  = (const float*)d_in[5];
    float* out = (float*)d_out;

    void *p_xp, *p_act, *p_gt, *p_ut, *p_dt;
    cudaGetSymbolAddress(&p_xp,  g_xp);
    cudaGetSymbolAddress(&p_act, g_act);
    cudaGetSymbolAddress(&p_gt,  g_gate_t);
    cudaGetSymbolAddress(&p_ut,  g_up_t);
    cudaGetSymbolAddress(&p_dt,  g_down_t);

    cudaFuncSetAttribute(k_gemm1_mma, cudaFuncAttributeMaxDynamicSharedMemorySize, G1_SMEM);
    cudaFuncSetAttribute(k_gemm2_mma, cudaFuncAttributeMaxDynamicSharedMemorySize, G2_SMEM);

    // routing prep
    k_zero_counts<<<1, 32>>>();
    k_hist<<<R_ROWS / 256, 256>>>(sel);
    k_prep<<<1, 1>>>();
    k_scatter<<<R_ROWS / 256, 256>>>(sel, rw);

    // staging
    k_permute<<<R_ROWS, 256>>>(hid);
    {
        dim3 b(32, 8);
        dim3 g_gu(I_DIM / 64, H_DIM / 64, N_EXP);   // [H,I] -> [I,H]
        k_transpose<H_DIM, I_DIM><<<g_gu, b>>>(gw, (__half*)p_gt);
        k_transpose<H_DIM, I_DIM><<<g_gu, b>>>(uw, (__half*)p_ut);
        dim3 g_d(H_DIM / 64, I_DIM / 64, N_EXP);    // [I,H] -> [H,I]
        k_transpose<I_DIM, H_DIM><<<g_d, b>>>(dw, (__half*)p_dt);
    }

    int n4 = (T_TOK * H_DIM) / 4;
    k_zero_out<<<n4 / 256, 256>>>((float4*)out, n4);

    dim3 g1(MAX_TILES, I_DIM / BN);   // 72 x 22
    k_gemm1_mma<<<g1, 256, G1_SMEM>>>((const __half*)p_xp, (const __half*)p_gt, (const __half*)p_ut);

    dim3 g2(MAX_TILES, H_DIM / BN);   // 72 x 32
    k_gemm2_mma<<<g2, 256, G2_SMEM>>>((const __half*)p_act, (const __half*)p_dt, out);
}

// round 11
// speedup vs baseline: 1.2717x; 1.1170x over previous
#include <cuda_runtime.h>
#include <cuda_fp16.h>
#include <math.h>
#include <stdint.h>
#include <string.h>

// ---------------------------------------------------------------------------
// MoE grouped MLP via fp16 mma.sync m16n8k16.
// B operand kept in natural [K][N] layout, loaded with ldmatrix.x4.trans
// (no weight transpose pass — straight scale+convert copy only).
// T=4096 H=2048 I=1408 E=8 K=2; rows = 8192.
// ---------------------------------------------------------------------------
#define T_TOK 4096
#define H_DIM 2048
#define I_DIM 1408
#define N_EXP 8
#define TOPK  2
#define R_ROWS (T_TOK * TOPK)
#define BM 128
#define MAX_TILES (R_ROWS / BM + N_EXP)   // 72

#define BN 64
#define BK 32
#define STAGES 4
#define NK1 (H_DIM / BK)                   // 64
#define NK2 (I_DIM / BK)                   // 44

// A-tile SMEM: padded stride 40 halfs (proven conflict-free for ldmatrix)
#define SH 40
#define AS_H (BM * SH)                     // 5120 halfs = 10240 B
// B-tile SMEM: [BK][BN] halfs, 128B rows, XOR chunk swizzle, 4096 B
#define BT_B (BK * BN * 2)                 // 4096 bytes
#define G1_SMEM (STAGES * (AS_H * 2 + 2 * BT_B))   // 73728 B
#define G2_SMEM (STAGES * (AS_H * 2 + BT_B))       // 57344 B

#define XP_ROWS  (R_ROWS + 128)
#define ACT_ROWS (R_ROWS + 128)

// static scaling: x*64, W*64, act*4096
#define S_IN   64.0f
#define DESC1  (1.0f / (64.0f * 64.0f))
#define S_ACT  4096.0f
#define DESC2  (1.0f / (4096.0f * 64.0f))

// ---- device-global scratch ----
__device__ int    g_counts[N_EXP];
__device__ int    g_cursor[N_EXP];
__device__ int    g_tile_e[MAX_TILES];
__device__ int    g_tile_row0[MAX_TILES];
__device__ int    g_tile_rows[MAX_TILES];
__device__ int    g_num_tiles;
__device__ int    g_row_t[R_ROWS];
__device__ float  g_row_p[R_ROWS];
__device__ __half g_xp[(size_t)XP_ROWS * H_DIM];
__device__ __half g_act[(size_t)ACT_ROWS * I_DIM];
__device__ __half g_gate_h[(size_t)N_EXP * H_DIM * I_DIM];   // [E][H][I] (natural)
__device__ __half g_up_h  [(size_t)N_EXP * H_DIM * I_DIM];
__device__ __half g_down_h[(size_t)N_EXP * I_DIM * H_DIM];   // [E][I][H] (natural)

// ---------------------------------------------------------------------------
__device__ __forceinline__ uint32_t h2_bits(__half2 h) {
    uint32_t u;
    memcpy(&u, &h, 4);
    return u;
}
__device__ __forceinline__ void cp16(void* dst, const void* src) {
    uint32_t d = (uint32_t)__cvta_generic_to_shared(dst);
    asm volatile("cp.async.cg.shared.global [%0], [%1], 16;" :: "r"(d), "l"(src) : "memory");
}
__device__ __forceinline__ void cp16s(uint32_t dst, const void* src) {
    asm volatile("cp.async.cg.shared.global [%0], [%1], 16;" :: "r"(dst), "l"(src) : "memory");
}
#define CP_COMMIT() asm volatile("cp.async.commit_group;" ::: "memory")
#define CP_WAIT2()  asm volatile("cp.async.wait_group 2;" ::: "memory")

#define MMA_F16(d, a, b0, b1)                                                \
    asm volatile("mma.sync.aligned.m16n8k16.row.col.f32.f16.f16.f32 "        \
        "{%0,%1,%2,%3}, {%4,%5,%6,%7}, {%8,%9}, {%0,%1,%2,%3};"              \
        : "+f"((d)[0]), "+f"((d)[1]), "+f"((d)[2]), "+f"((d)[3])             \
        : "r"((a)[0]), "r"((a)[1]), "r"((a)[2]), "r"((a)[3]),                \
          "r"(b0), "r"(b1))

#define LDSM4(r, addr)                                                        \
    asm volatile("ldmatrix.sync.aligned.m8n8.x4.shared.b16 {%0,%1,%2,%3}, [%4];" \
        : "=r"((r)[0]), "=r"((r)[1]), "=r"((r)[2]), "=r"((r)[3]) : "r"(addr))

#define LDSM4T(r, addr)                                                       \
    asm volatile("ldmatrix.sync.aligned.m8n8.x4.trans.shared.b16 {%0,%1,%2,%3}, [%4];" \
        : "=r"((r)[0]), "=r"((r)[1]), "=r"((r)[2]), "=r"((r)[3]) : "r"(addr))

#define REDV2(ptr, v0, v1)                                                    \
    asm volatile("red.global.add.v2.f32 [%0], {%1, %2};"                      \
        :: "l"(ptr), "f"(v0), "f"(v1) : "memory")

// ---------------------------------------------------------------------------
// prep kernels
// ---------------------------------------------------------------------------
__global__ void k_zero_counts() { if (threadIdx.x < N_EXP) g_counts[threadIdx.x] = 0; }

__global__ void k_hist(const int* __restrict__ sel) {
    int f = blockIdx.x * blockDim.x + threadIdx.x;
    if (f < R_ROWS) {
        int t = f % T_TOK, k = f / T_TOK;
        atomicAdd(&g_counts[sel[t * TOPK + k]], 1);
    }
}

__global__ void k_prep() {
    int off = 0, nt = 0;
    for (int e = 0; e < N_EXP; ++e) {
        int c = g_counts[e];
        g_cursor[e] = off;
        for (int r0 = 0; r0 < c; r0 += BM) {
            g_tile_e[nt] = e; g_tile_row0[nt] = off + r0;
            g_tile_rows[nt] = min(BM, c - r0); ++nt;
        }
        off += c;
    }
    g_num_tiles = nt;
}

__global__ void k_scatter(const int* __restrict__ sel, const float* __restrict__ rw) {
    int f = blockIdx.x * blockDim.x + threadIdx.x;
    if (f < R_ROWS) {
        int t = f % T_TOK, k = f / T_TOK;
        int e = sel[t * TOPK + k];
        int d = atomicAdd(&g_cursor[e], 1);
        g_row_t[d] = t;
        g_row_p[d] = rw[t * TOPK + k];
    }
}

__global__ void k_zero_out(float4* __restrict__ out, int n4) {
    int i = blockIdx.x * blockDim.x + threadIdx.x;
    if (i < n4) out[i] = make_float4(0.f, 0.f, 0.f, 0.f);
}

// gather rows, scale by 64, convert fp16, 16B stores
__global__ void k_permute(const float* __restrict__ hid) {
    int r = blockIdx.x;
    int t = g_row_t[r];
    const float4* src = (const float4*)(hid + (size_t)t * H_DIM);
    uint4* dst = (uint4*)(g_xp + (size_t)r * H_DIM);
    for (int i = threadIdx.x; i < H_DIM / 8; i += blockDim.x) {
        float4 v0 = src[2 * i], v1 = src[2 * i + 1];
        uint4 o;
        o.x = h2_bits(__floats2half2_rn(v0.x * S_IN, v0.y * S_IN));
        o.y = h2_bits(__floats2half2_rn(v0.z * S_IN, v0.w * S_IN));
        o.z = h2_bits(__floats2half2_rn(v1.x * S_IN, v1.y * S_IN));
        o.w = h2_bits(__floats2half2_rn(v1.z * S_IN, v1.w * S_IN));
        dst[i] = o;
    }
}

// straight streaming convert: out[i] = half(in[i] * S_IN), 8 elems/thread
__global__ void k_convert(const float* __restrict__ in, __half* __restrict__ out,
                          size_t n8) {
    size_t i = (size_t)blockIdx.x * blockDim.x + threadIdx.x;
    if (i < n8) {
        const float4* src = (const float4*)in + 2 * i;
        float4 v0 = src[0], v1 = src[1];
        uint4 o;
        o.x = h2_bits(__floats2half2_rn(v0.x * S_IN, v0.y * S_IN));
        o.y = h2_bits(__floats2half2_rn(v0.z * S_IN, v0.w * S_IN));
        o.z = h2_bits(__floats2half2_rn(v1.x * S_IN, v1.y * S_IN));
        o.w = h2_bits(__floats2half2_rn(v1.z * S_IN, v1.w * S_IN));
        ((uint4*)out)[i] = o;
    }
}

// ---------------------------------------------------------------------------
// GEMM1: act = silu(xp @ gate^T) * (xp @ up^T); 128x64 tiles.
// A: [M][K] SMEM stride-40, ldmatrix.  B: [K][N] SMEM 128B rows + XOR swizzle,
// ldmatrix.trans.  256 threads = 8 warps (4M x 2N), warp tile 32x32.
// ---------------------------------------------------------------------------
__global__ __launch_bounds__(256, 2)
void k_gemm1_mma(const __half* __restrict__ xp,
                 const __half* __restrict__ gt,
                 const __half* __restrict__ ut) {
    const int tile = blockIdx.x;
    if (tile >= g_num_tiles) return;
    const int e    = g_tile_e[tile];
    const int row0 = g_tile_row0[tile];
    const int rows = g_tile_rows[tile];
    const int n0   = blockIdx.y * BN;

    extern __shared__ __half sm[];
    __half* As = sm;                                   // STAGES * AS_H halfs
    const uint32_t su  = (uint32_t)__cvta_generic_to_shared(sm);
    const uint32_t bgu = su + STAGES * AS_H * 2;       // gate B tiles
    const uint32_t buu = bgu + STAGES * BT_B;          // up B tiles

    const int tid  = threadIdx.x;
    const int lane = tid & 31, wid = tid >> 5;
    const int wm = wid & 3, wn = wid >> 2;
    const int lg = lane >> 2, lt = lane & 3;

    // A ldmatrix lane offset (bytes), proven layout
    const uint32_t aoff = (((lane & 7) + ((lane >> 3) & 1) * 8) * SH + (lane >> 4) * 8) * 2;
    // B ldmatrix.trans lane parameters
    const uint32_t blk_row  = (lane & 7) + ((lane >> 3) & 1) * 8;  // k within 16
    const uint32_t bxor     = lane & 7;
    const uint32_t bnc_base = wn * 4 + (lane >> 4);                // n chunk

    const __half* arow = xp + (size_t)row0 * H_DIM;
    const __half* gte  = gt + (size_t)e * H_DIM * I_DIM + n0;  // row stride I_DIM
    const __half* ute  = ut + (size_t)e * H_DIM * I_DIM + n0;

    // loaders
    const int alr = tid >> 1, alc = (tid & 1) * 2;       // A: 2 cp16/thread
    const int bk  = tid >> 3, bc = tid & 7;              // B: 1 cp16/thread/matrix
    const uint32_t bsw = (uint32_t)(bk * 128 + ((bc ^ (bk & 7)) << 4));

    float accg[2][4][4], accu[2][4][4];
    #pragma unroll
    for (int a = 0; a < 2; ++a)
        #pragma unroll
        for (int b = 0; b < 4; ++b)
            #pragma unroll
            for (int c = 0; c < 4; ++c) { accg[a][b][c] = 0.f; accu[a][b][c] = 0.f; }

    #define G1_LOAD(s, ki) do {                                                   \
        int k0_ = (ki) * BK;                                                      \
        __half* as_ = As + (s) * AS_H;                                            \
        cp16(&as_[alr * SH + alc * 8],       arow + (size_t)alr * H_DIM + k0_ + alc * 8);      \
        cp16(&as_[alr * SH + (alc + 1) * 8], arow + (size_t)alr * H_DIM + k0_ + (alc + 1) * 8);\
        cp16s(bgu + (s) * BT_B + bsw, gte + (size_t)(k0_ + bk) * I_DIM + bc * 8);  \
        cp16s(buu + (s) * BT_B + bsw, ute + (size_t)(k0_ + bk) * I_DIM + bc * 8);  \
    } while (0)

    G1_LOAD(0, 0); CP_COMMIT();
    G1_LOAD(1, 1); CP_COMMIT();
    G1_LOAD(2, 2); CP_COMMIT();

    int slot = 0;
    #pragma unroll 1
    for (int ki = 0; ki < NK1; ++ki) {
        CP_WAIT2();
        __syncthreads();
        if (ki + 3 < NK1) {
            int ns = slot + 3; if (ns >= STAGES) ns -= STAGES;
            G1_LOAD(ns, ki + 3);
        }
        CP_COMMIT();

        const uint32_t asb = su  + slot * AS_H * 2 + (wm * 32) * SH * 2 + aoff;
        const uint32_t bgs = bgu + slot * BT_B;
        const uint32_t bus = buu + slot * BT_B;
        #pragma unroll
        for (int ks = 0; ks < 2; ++ks) {
            const uint32_t kb2 = ks * 32;                 // A: ks*16 halfs
            const uint32_t bkrow = (ks * 16 + blk_row) * 128;
            uint32_t af[2][4], bgr[8], bur[8];
            LDSM4(af[0], asb + kb2);
            LDSM4(af[1], asb + 16 * SH * 2 + kb2);
            LDSM4T(&bgr[0], bgs + bkrow + (((bnc_base + 0) ^ bxor) << 4));
            LDSM4T(&bgr[4], bgs + bkrow + (((bnc_base + 2) ^ bxor) << 4));
            LDSM4T(&bur[0], bus + bkrow + (((bnc_base + 0) ^ bxor) << 4));
            LDSM4T(&bur[4], bus + bkrow + (((bnc_base + 2) ^ bxor) << 4));
            #pragma unroll
            for (int nt = 0; nt < 4; ++nt) {
                #pragma unroll
                for (int mt = 0; mt < 2; ++mt) {
                    MMA_F16(accg[mt][nt], af[mt], bgr[2 * nt], bgr[2 * nt + 1]);
                    MMA_F16(accu[mt][nt], af[mt], bur[2 * nt], bur[2 * nt + 1]);
                }
            }
        }
        if (++slot == STAGES) slot = 0;
    }
    #undef G1_LOAD

    // epilogue: descale, silu(g)*u, rescale, store fp16
    #pragma unroll
    for (int mt = 0; mt < 2; ++mt) {
        #pragma unroll
        for (int half = 0; half < 2; ++half) {
            int m = wm * 32 + mt * 16 + lg + half * 8;
            if (m < rows) {
                __half* dst = g_act + (size_t)(row0 + m) * I_DIM + n0 + wn * 32;
                #pragma unroll
                for (int nt = 0; nt < 4; ++nt) {
                    float g0 = accg[mt][nt][half * 2 + 0] * DESC1;
                    float u0 = accu[mt][nt][half * 2 + 0] * DESC1;
                    float g1 = accg[mt][nt][half * 2 + 1] * DESC1;
                    float u1 = accu[mt][nt][half * 2 + 1] * DESC1;
                    float a0 = (g0 / (1.f + __expf(-g0))) * u0 * S_ACT;
                    float a1 = (g1 / (1.f + __expf(-g1))) * u1 * S_ACT;
                    *(__half2*)(dst + nt * 8 + 2 * lt) = __floats2half2_rn(a0, a1);
                }
            }
        }
    }
}

// ---------------------------------------------------------------------------
// GEMM2: out[t] += p * descale * (act @ down^T)
// ---------------------------------------------------------------------------
__global__ __launch_bounds__(256, 2)
void k_gemm2_mma(const __half* __restrict__ act,
                 const __half* __restrict__ dt,
                 float* __restrict__ out) {
    const int tile = blockIdx.x;
    if (tile >= g_num_tiles) return;
    const int e    = g_tile_e[tile];
    const int row0 = g_tile_row0[tile];
    const int rows = g_tile_rows[tile];
    const int n0   = blockIdx.y * BN;

    extern __shared__ __half sm[];
    __half* As = sm;
    const uint32_t su  = (uint32_t)__cvta_generic_to_shared(sm);
    const uint32_t bsu = su + STAGES * AS_H * 2;

    const int tid  = threadIdx.x;
    const int lane = tid & 31, wid = tid >> 5;
    const int wm = wid & 3, wn = wid >> 2;
    const int lg = lane >> 2, lt = lane & 3;

    const uint32_t aoff = (((lane & 7) + ((lane >> 3) & 1) * 8) * SH + (lane >> 4) * 8) * 2;
    const uint32_t blk_row  = (lane & 7) + ((lane >> 3) & 1) * 8;
    const uint32_t bxor     = lane & 7;
    const uint32_t bnc_base = wn * 4 + (lane >> 4);

    const __half* arow = act + (size_t)row0 * I_DIM;
    const __half* dte  = dt + (size_t)e * I_DIM * H_DIM + n0;   // row stride H_DIM

    const int alr = tid >> 1, alc = (tid & 1) * 2;
    const int bk  = tid >> 3, bc = tid & 7;
    const uint32_t bsw = (uint32_t)(bk * 128 + ((bc ^ (bk & 7)) << 4));

    float acc[2][4][4];
    #pragma unroll
    for (int a = 0; a < 2; ++a)
        #pragma unroll
        for (int b = 0; b < 4; ++b)
            #pragma unroll
            for (int c = 0; c < 4; ++c) acc[a][b][c] = 0.f;

    #define G2_LOAD(s, ki) do {                                                   \
        int k0_ = (ki) * BK;                                                      \
        __half* as_ = As + (s) * AS_H;                                            \
        cp16(&as_[alr * SH + alc * 8],       arow + (size_t)alr * I_DIM + k0_ + alc * 8);      \
        cp16(&as_[alr * SH + (alc + 1) * 8], arow + (size_t)alr * I_DIM + k0_ + (alc + 1) * 8);\
        cp16s(bsu + (s) * BT_B + bsw, dte + (size_t)(k0_ + bk) * H_DIM + bc * 8);  \
    } while (0)

    G2_LOAD(0, 0); CP_COMMIT();
    G2_LOAD(1, 1); CP_COMMIT();
    G2_LOAD(2, 2); CP_COMMIT();

    int slot = 0;
    #pragma unroll 1
    for (int ki = 0; ki < NK2; ++ki) {
        CP_WAIT2();
        __syncthreads();
        if (ki + 3 < NK2) {
            int ns = slot + 3; if (ns >= STAGES) ns -= STAGES;
            G2_LOAD(ns, ki + 3);
        }
        CP_COMMIT();

        const uint32_t asb = su  + slot * AS_H * 2 + (wm * 32) * SH * 2 + aoff;
        const uint32_t bss = bsu + slot * BT_B;
        #pragma unroll
        for (int ks = 0; ks < 2; ++ks) {
            const uint32_t kb2 = ks * 32;
            const uint32_t bkrow = (ks * 16 + blk_row) * 128;
            uint32_t af[2][4], br[8];
            LDSM4(af[0], asb + kb2);
            LDSM4(af[1], asb + 16 * SH * 2 + kb2);
            LDSM4T(&br[0], bss + bkrow + (((bnc_base + 0) ^ bxor) << 4));
            LDSM4T(&br[4], bss + bkrow + (((bnc_base + 2) ^ bxor) << 4));
            #pragma unroll
            for (int nt = 0; nt < 4; ++nt) {
                #pragma unroll
                for (int mt = 0; mt < 2; ++mt)
                    MMA_F16(acc[mt][nt], af[mt], br[2 * nt], br[2 * nt + 1]);
            }
        }
        if (++slot == STAGES) slot = 0;
    }
    #undef G2_LOAD

    // epilogue: weighted vector reduce-add with descale
    #pragma unroll
    for (int mt = 0; mt < 2; ++mt) {
        #pragma unroll
        for (int half = 0; half < 2; ++half) {
            int m = wm * 32 + mt * 16 + lg + half * 8;
            if (m < rows) {
                float p = g_row_p[row0 + m] * DESC2;
                int   t = g_row_t[row0 + m];
                float* dst = out + (size_t)t * H_DIM + n0 + wn * 32;
                #pragma unroll
                for (int nt = 0; nt < 4; ++nt) {
                    REDV2(dst + nt * 8 + 2 * lt,
                          acc[mt][nt][half * 2 + 0] * p,
                          acc[mt][nt][half * 2 + 1] * p);
                }
            }
        }
    }
}

// ---------------------------------------------------------------------------
extern "C" void kernel_launch(void* const* d_in, const int* in_sizes, int n_in,
                              void* d_out, int out_size) {
    const float* hid = (const float*)d_in[0];
    const float* rw  = (const float*)d_in[1];
    const int*   sel = (const int*)  d_in[2];
    const float* gw  = (const float*)d_in[3];
    const float* uw  = (const float*)d_in[4];
    const float* dw  = (const float*)d_in[5];
    float* out = (float*)d_out;

    void *p_xp, *p_act, *p_gh, *p_uh, *p_dh;
    cudaGetSymbolAddress(&p_xp,  g_xp);
    cudaGetSymbolAddress(&p_act, g_act);
    cudaGetSymbolAddress(&p_gh,  g_gate_h);
    cudaGetSymbolAddress(&p_uh,  g_up_h);
    cudaGetSymbolAddress(&p_dh,  g_down_h);

    cudaFuncSetAttribute(k_gemm1_mma, cudaFuncAttributeMaxDynamicSharedMemorySize, G1_SMEM);
    cudaFuncSetAttribute(k_gemm2_mma, cudaFuncAttributeMaxDynamicSharedMemorySize, G2_SMEM);

    // routing prep
    k_zero_counts<<<1, 32>>>();
    k_hist<<<R_ROWS / 256, 256>>>(sel);
    k_prep<<<1, 1>>>();
    k_scatter<<<R_ROWS / 256, 256>>>(sel, rw);

    // staging: gather+scale+fp16 A; straight scale+fp16 weight converts
    k_permute<<<R_ROWS, 256>>>(hid);
    {
        size_t n8 = (size_t)N_EXP * H_DIM * I_DIM / 8;   // 2883584
        int blocks = (int)((n8 + 255) / 256);
        k_convert<<<blocks, 256>>>(gw, (__half*)p_gh, n8);
        k_convert<<<blocks, 256>>>(uw, (__half*)p_uh, n8);
        k_convert<<<blocks, 256>>>(dw, (__half*)p_dh, n8);
    }

    int n4 = (T_TOK * H_DIM) / 4;
    k_zero_out<<<n4 / 256, 256>>>((float4*)out, n4);

    dim3 g1(MAX_TILES, I_DIM / BN);   // 72 x 22
    k_gemm1_mma<<<g1, 256, G1_SMEM>>>((const __half*)p_xp, (const __half*)p_gh, (const __half*)p_uh);

    dim3 g2(MAX_TILES, H_DIM / BN);   // 72 x 32
    k_gemm2_mma<<<g2, 256, G2_SMEM>>>((const __half*)p_act, (const __half*)p_dh, out);
}